// round 14
// baseline (speedup 1.0000x reference)
#include <cuda_runtime.h>
#include <cuda_fp16.h>
#include <cstdint>
#include <math.h>

#define LL 24
#define NN 8192
#define DIN 256
#define DOUT 128
#define NWX 512     // 4*DOUT
#define NPG 640     // 5 gates * 128 (gathered-P width)

// ---------------- device globals ----------------
__device__ __half g_WxH[(size_t)LL * NN * NWX];          // fp16, [lvl*NN+n][c], c=d*4+gate
__device__ __half g_PH[(size_t)NN * NPG];                // fp16 gathered P, [n][w*128+d]
__device__ float g_biasPerm[NWX];
__device__ __half g_Ah[(size_t)LL * NN * DIN];           // tensor, fp16
__device__ __half g_Bwh[(size_t)NWX * DIN];              // permuted Ww, fp16
__device__ __half g_Uh[(size_t)NPG * 256];               // U rows j=w*128+d, cols k=0..255
__device__ __half g_HhX[(size_t)(NN + 1) * DOUT];        // row 0 = h_init, row n+1 = h_prev[n]

__device__ __forceinline__ float sigmoidf_(float x) {
    return 1.0f / (1.0f + __expf(-x));
}

__device__ __forceinline__ uint32_t smem_to_u32(const void* p) {
    uint32_t a;
    asm("{ .reg .u64 t; cvta.to.shared.u64 t, %1; cvt.u32.u64 %0, t; }" : "=r"(a) : "l"(p));
    return a;
}

#define CP_COMMIT() asm volatile("cp.async.commit_group;" ::: "memory")
__device__ __forceinline__ void cpa16(uint32_t d, const void* s) {
    asm volatile("cp.async.cg.shared.global [%0], [%1], 16;" :: "r"(d), "l"(s));
}
__device__ __forceinline__ void ldm_x4(uint32_t a, uint32_t& r0, uint32_t& r1,
                                       uint32_t& r2, uint32_t& r3) {
    asm volatile("ldmatrix.sync.aligned.m8n8.x4.shared.b16 {%0,%1,%2,%3}, [%4];"
                 : "=r"(r0), "=r"(r1), "=r"(r2), "=r"(r3) : "r"(a));
}
__device__ __forceinline__ void mma16816(float* c, const uint32_t* a, const uint32_t* b) {
    asm volatile(
        "mma.sync.aligned.m16n8k16.row.col.f32.f16.f16.f32 "
        "{%0,%1,%2,%3}, {%4,%5,%6,%7}, {%8,%9}, {%0,%1,%2,%3};"
        : "+f"(c[0]), "+f"(c[1]), "+f"(c[2]), "+f"(c[3])
        : "r"(a[0]), "r"(a[1]), "r"(a[2]), "r"(a[3]), "r"(b[0]), "r"(b[1]));
}

// ---------------- prep kernels (globals bound in device code) ----------------
__global__ void build_ah(const float* __restrict__ X) {
    size_t i = (size_t)blockIdx.x * 256 + threadIdx.x;   // one float4 per thread
    float4 v = ((const float4*)X)[i];
    union { __half h[4]; uint2 u; } o;
    o.h[0] = __float2half(v.x); o.h[1] = __float2half(v.y);
    o.h[2] = __float2half(v.z); o.h[3] = __float2half(v.w);
    *(uint2*)&g_Ah[i * 4] = o.u;
}

__global__ void build_bw(const float* __restrict__ Ww, const float* __restrict__ Wb) {
    int t = blockIdx.x * blockDim.x + threadIdx.x;
    if (t < NWX) g_biasPerm[t] = Wb[((t & 3) << 7) + (t >> 2)];
    if (t >= NWX * DIN) return;
    int c = t >> 8, k = t & 255;
    int orig = ((c & 3) << 7) + (c >> 2);
    g_Bwh[t] = __float2half(Ww[orig * DIN + k]);
}

// U rows j = w*128+d (w: 0=f1,1=f2,2=i,3=u,4=o), cols k over full 2*DOUT.
__global__ void build_u(const float* __restrict__ Uf1,
                        const float* __restrict__ Uf2,
                        const float* __restrict__ Uiuo) {
    int t = blockIdx.x * blockDim.x + threadIdx.x;
    if (t >= NPG * 256) return;
    int j = t >> 8;
    int k = t & 255;
    int w = j >> 7;
    int d = j & 127;
    float v;
    if (w == 0)      v = Uf1[d * DIN + k];
    else if (w == 1) v = Uf2[d * DIN + k];
    else             v = Uiuo[((w - 2) * DOUT + d) * DIN + k];
    g_Uh[t] = __float2half(v);
}

__global__ void build_h0(const float* __restrict__ hInit) {
    int d = threadIdx.x;
    g_HhX[d] = __float2half(hInit[d]);
}

// ---------------- fp16 mma.sync GEMM ----------------
// MODE 0: X @ Ww^T + b -> g_WxH. M=L*N, N=512, K=256. A rows dense from g_Ah.
// MODE 1: hc @ U^T -> g_PH (gathered node order). M=NN, N=640, K=256.
//         A row n = [h_prev[i0(n)] | h_prev[i1(n)]], via indexed cp.async from
//         g_HhX (row = idx+1; idx=-1 or level 0 -> row 0 = init).
// Tiles: BM=BN=128, BK=32. 8 warps: wm=wid&1 (64 rows), wn=wid>>1 (32 cols).
#define SM_PITCH 80
#define SM_ARR   10240              // 128 rows * 80B
#define SM_BUF   20480              // A, B
#define SM_TOT   40960

template<int MODE>
__global__ __launch_bounds__(256, 2) void mma_gemm(int lvl, const int* __restrict__ indices) {
    constexpr int K   = 256;
    constexpr int nCh = K / 32;
    constexpr int ldc = (MODE == 0) ? NWX : NPG;

    const __half* __restrict__ B = (MODE == 0) ? g_Bwh : g_Uh;

    extern __shared__ char smem[];
    uint32_t sb = smem_to_u32(smem);
    int tid = threadIdx.x;
    int lane = tid & 31, wid = tid >> 5;
    int wm = wid & 1, wn = wid >> 1;
    int bn = blockIdx.x * 128;
    int bm = blockIdx.y * 128;

    float acc[4][4][4];
#pragma unroll
    for (int mi = 0; mi < 4; mi++)
#pragma unroll
        for (int ni = 0; ni < 4; ni++)
#pragma unroll
            for (int e = 0; e < 4; e++) acc[mi][ni][e] = 0.f;

    // cp.async: 512 16B-chunks per 128x32 fp16 tile; 2 chunks/thread/array.
    int ch0 = tid * 2;
    int rowA0 = ch0 >> 2, cc0 = (ch0 & 3);
    int rowA1 = (ch0 + 1) >> 2, cc1 = ((ch0 + 1) & 3);
    uint32_t s0 = (uint32_t)(rowA0 * SM_PITCH + cc0 * 16);
    uint32_t s1 = (uint32_t)(rowA1 * SM_PITCH + cc1 * 16);

    // A source pointers
    const __half *pA0L, *pA0R, *pA1L, *pA1R;   // MODE 1: left/right child
    const __half *gA0 = nullptr, *gA1 = nullptr; // MODE 0: dense
    if constexpr (MODE == 0) {
        gA0 = g_Ah + (size_t)(bm + rowA0) * K + cc0 * 8;
        gA1 = g_Ah + (size_t)(bm + rowA1) * K + cc1 * 8;
        pA0L = pA0R = pA1L = pA1R = nullptr;
    } else {
        bool L0 = (lvl == 0);
        int2 id0 = ((const int2*)indices)[(size_t)lvl * NN + (bm + rowA0)];
        int2 id1 = ((const int2*)indices)[(size_t)lvl * NN + (bm + rowA1)];
        int r0L = L0 ? 0 : (id0.x + 1), r0R = L0 ? 0 : (id0.y + 1);
        int r1L = L0 ? 0 : (id1.x + 1), r1R = L0 ? 0 : (id1.y + 1);
        pA0L = g_HhX + (size_t)r0L * DOUT + cc0 * 8;
        pA0R = g_HhX + (size_t)r0R * DOUT + cc0 * 8;
        pA1L = g_HhX + (size_t)r1L * DOUT + cc1 * 8;
        pA1R = g_HhX + (size_t)r1R * DOUT + cc1 * 8;
    }
    const __half* gB0 = B + (size_t)(bn + rowA0) * K + cc0 * 8;
    const __half* gB1 = B + (size_t)(bn + rowA1) * K + cc1 * 8;

#define LOAD_STAGE(t, b) do {                                               \
    uint32_t bo = sb + (uint32_t)(b) * SM_BUF;                              \
    int ko = (t) * 32;                                                      \
    if constexpr (MODE == 0) {                                              \
        cpa16(bo + s0, gA0 + ko);                                           \
        cpa16(bo + s1, gA1 + ko);                                           \
    } else {                                                                \
        int kk = ko & 127;                                                  \
        cpa16(bo + s0, ((ko < 128) ? pA0L : pA0R) + kk);                    \
        cpa16(bo + s1, ((ko < 128) ? pA1L : pA1R) + kk);                    \
    }                                                                       \
    cpa16(bo + SM_ARR + s0, gB0 + ko);                                      \
    cpa16(bo + SM_ARR + s1, gB1 + ko);                                      \
} while (0)

    // ldmatrix lane addressing (verified in R8-R12)
    int q = lane >> 3, r = lane & 7;
    uint32_t aLane = (uint32_t)(wm * 64 * SM_PITCH + (r + (q & 1) * 8) * SM_PITCH + (q >> 1) * 16);
    uint32_t bLane = (uint32_t)(wn * 32 * SM_PITCH + ((q >> 1) * 8 + r) * SM_PITCH + (q & 1) * 16);

    LOAD_STAGE(0, 0); CP_COMMIT();
    LOAD_STAGE(1, 1); CP_COMMIT();

    for (int t = 0; t < nCh; t++) {
        if (t == nCh - 1) asm volatile("cp.async.wait_group 0;" ::: "memory");
        else              asm volatile("cp.async.wait_group 1;" ::: "memory");
        __syncthreads();

        uint32_t base = sb + (uint32_t)(t & 1) * SM_BUF;
#pragma unroll
        for (int ks = 0; ks < 2; ks++) {
            uint32_t a[4][4], b[4][2];
#pragma unroll
            for (int mi = 0; mi < 4; mi++)
                ldm_x4(base + aLane + mi * (16 * SM_PITCH) + ks * 32,
                       a[mi][0], a[mi][1], a[mi][2], a[mi][3]);
#pragma unroll
            for (int np = 0; np < 2; np++) {
                uint32_t r0, r1, r2, r3;
                ldm_x4(base + SM_ARR + bLane + np * (16 * SM_PITCH) + ks * 32, r0, r1, r2, r3);
                b[2 * np][0] = r0; b[2 * np][1] = r1;
                b[2 * np + 1][0] = r2; b[2 * np + 1][1] = r3;
            }
#pragma unroll
            for (int mi = 0; mi < 4; mi++)
#pragma unroll
                for (int ni = 0; ni < 4; ni++)
                    mma16816(acc[mi][ni], a[mi], b[ni]);
        }
        __syncthreads();
        if (t + 2 < nCh) { LOAD_STAGE(t + 2, t & 1); CP_COMMIT(); }
    }

    // epilogue: fp16 output both modes
    int g = lane >> 2, tc = lane & 3;
#pragma unroll
    for (int mi = 0; mi < 4; mi++) {
        int row0 = bm + wm * 64 + mi * 16 + g;
#pragma unroll
        for (int ni = 0; ni < 4; ni++) {
            int col = bn + wn * 32 + ni * 8 + tc * 2;
            float b0 = 0.f, b1 = 0.f;
            if (MODE == 0) { b0 = g_biasPerm[col]; b1 = g_biasPerm[col + 1]; }
            __half2 h0 = __floats2half2_rn(acc[mi][ni][0] + b0, acc[mi][ni][1] + b1);
            __half2 h1 = __floats2half2_rn(acc[mi][ni][2] + b0, acc[mi][ni][3] + b1);
            __half* dst = (MODE == 0) ? g_WxH : g_PH;
            *(__half2*)&dst[(size_t)row0 * ldc + col] = h0;
            *(__half2*)&dst[(size_t)(row0 + 8) * ldc + col] = h1;
        }
    }
#undef LOAD_STAGE
}

// ---------------- LSTM gate epilogue (branch-free P reads) ----------------
__global__ __launch_bounds__(256) void epilogue_kernel(
    int lvl,
    const int* __restrict__ indices,
    const float* __restrict__ cInit,
    float* __restrict__ outH,
    float* __restrict__ outC)
{
    int tid = threadIdx.x;
    int n = blockIdx.x * 2 + (tid >> 7);
    int d = tid & 127;

    // sequential, node-major P
    const __half* rr = g_PH + (size_t)n * NPG;
    float p0 = __half2float(rr[d]);
    float p1 = __half2float(rr[128 + d]);
    float p2 = __half2float(rr[256 + d]);
    float p3 = __half2float(rr[384 + d]);
    float p4 = __half2float(rr[512 + d]);

    // g_WxH: 4 fp16 per (n,d): f_x, i_x, u_x, o_x
    union { uint2 u; __half h[4]; } wv;
    wv.u = *(const uint2*)&g_WxH[(((size_t)lvl * NN + n) << 9) + (d << 2)];
    float fx = __half2float(wv.h[0]);
    float ix = __half2float(wv.h[1]);
    float ux = __half2float(wv.h[2]);
    float ox = __half2float(wv.h[3]);

    float f1 = sigmoidf_(fx + p0);
    float f2 = sigmoidf_(fx + p1);
    float ig = sigmoidf_(ix + p2);
    float ug = tanhf(ux + p3);
    float og = sigmoidf_(ox + p4);

    int i0 = indices[((size_t)lvl * NN + n) * 2 + 0];
    int i1 = indices[((size_t)lvl * NN + n) * 2 + 1];
    bool L0 = (lvl == 0);
    const float* prevC = outC + (size_t)(lvl - 1) * NN * DOUT;
    float cc0 = (!L0 && i0 >= 0) ? prevC[(size_t)i0 * DOUT + d] : cInit[d];
    float cc1 = (!L0 && i1 >= 0) ? prevC[(size_t)i1 * DOUT + d] : cInit[d];

    float nc = ig * ug + f1 * cc0 + f2 * cc1;
    float nh = og * tanhf(nc);

    size_t o = ((size_t)lvl * NN + n) * DOUT + d;
    outH[o] = nh;
    outC[o] = nc;

    // fp16 h for next level's gathered GEMM (row n+1; row 0 = init)
    g_HhX[(size_t)(n + 1) * DOUT + d] = __float2half(nh);
}

extern "C" void kernel_launch(void* const* d_in, const int* in_sizes, int n_in,
                              void* d_out, int out_size) {
    const float* tensor = (const float*)d_in[0];   // [L, N, DIN]
    const int*   indices = (const int*)d_in[1];    // [L, N, 2]
    const float* h_init = (const float*)d_in[2];   // [1, DOUT]
    const float* c_init = (const float*)d_in[3];   // [1, DOUT]
    const float* W_w   = (const float*)d_in[4];    // [4*DOUT, DIN]
    const float* W_b   = (const float*)d_in[5];    // [4*DOUT]
    const float* U_f1  = (const float*)d_in[6];    // [DOUT, 2*DOUT]
    const float* U_f2  = (const float*)d_in[7];
    const float* U_iuo = (const float*)d_in[8];    // [3*DOUT, 2*DOUT]

    float* outH = (float*)d_out;                         // res_h [L,N,DOUT]
    float* outC = outH + (size_t)LL * NN * DOUT;         // res_c [L,N,DOUT]

    cudaFuncSetAttribute(mma_gemm<0>, cudaFuncAttributeMaxDynamicSharedMemorySize, SM_TOT);
    cudaFuncSetAttribute(mma_gemm<1>, cudaFuncAttributeMaxDynamicSharedMemorySize, SM_TOT);

    build_ah<<<(LL * NN * DIN / 4) / 256, 256>>>(tensor);
    build_bw<<<(NWX * DIN + 255) / 256, 256>>>(W_w, W_b);
    build_u<<<(NPG * 256 + 255) / 256, 256>>>(U_f1, U_f2, U_iuo);
    build_h0<<<1, 128>>>(h_init);

    // pre: W_x = X @ Ww^T + b.  M = L*N, N = 512, K = 256.
    {
        dim3 g(NWX / 128, (LL * NN) / 128);              // (4, 1536)
        mma_gemm<0><<<g, 256, SM_TOT>>>(0, nullptr);
    }

    dim3 pg(NPG / 128, NN / 128);                        // (5, 64)
    for (int lvl = 0; lvl < LL; lvl++) {
        mma_gemm<1><<<pg, 256, SM_TOT>>>(lvl, indices);
        epilogue_kernel<<<NN / 2, 256>>>(lvl, indices, c_init, outH, outC);
    }
}

// round 15
// speedup vs baseline: 1.3914x; 1.3914x over previous
#include <cuda_runtime.h>
#include <cuda_fp16.h>
#include <cstdint>
#include <math.h>

#define LL 24
#define NN 8192
#define DIN 256
#define DOUT 128
#define NWX 512     // 4*DOUT
#define NP  1280    // 2 halves * 5 gates * 128

// ---------------- device globals ----------------
__device__ __half g_WxH[(size_t)LL * NN * NWX];          // fp16, [lvl*NN+n][c], c=d*4+gate
__device__ float g_P[(size_t)NN * NP];
__device__ float g_Pinit[NP];
__device__ float g_Upair[(size_t)NP * 128];              // fp32 (for Pinit)
__device__ float g_biasPerm[NWX];
__device__ __half g_Ah[(size_t)LL * NN * DIN];           // tensor, fp16
__device__ __half g_Bwh[(size_t)NWX * DIN];              // permuted Ww, fp16
__device__ __half g_Uph[(size_t)NP * 128];               // Upair, fp16
__device__ __half g_Hh[(size_t)NN * DOUT];               // prev-level h, fp16

// ---------------- static stream/event resources (host-side only) ----------
struct OverlapRes {
    cudaStream_t s1;
    cudaEvent_t evStart;
    cudaEvent_t ev[LL];
    OverlapRes() {
        cudaStreamCreateWithFlags(&s1, cudaStreamNonBlocking);
        cudaEventCreateWithFlags(&evStart, cudaEventDisableTiming);
        for (int i = 0; i < LL; i++)
            cudaEventCreateWithFlags(&ev[i], cudaEventDisableTiming);
    }
};
static OverlapRes g_res;

__device__ __forceinline__ float sigmoidf_(float x) {
    return 1.0f / (1.0f + __expf(-x));
}

__device__ __forceinline__ uint32_t smem_to_u32(const void* p) {
    uint32_t a;
    asm("{ .reg .u64 t; cvta.to.shared.u64 t, %1; cvt.u32.u64 %0, t; }" : "=r"(a) : "l"(p));
    return a;
}

#define CP_COMMIT() asm volatile("cp.async.commit_group;" ::: "memory")
__device__ __forceinline__ void cpa16(uint32_t d, const void* s) {
    asm volatile("cp.async.cg.shared.global [%0], [%1], 16;" :: "r"(d), "l"(s));
}
__device__ __forceinline__ void ldm_x4(uint32_t a, uint32_t& r0, uint32_t& r1,
                                       uint32_t& r2, uint32_t& r3) {
    asm volatile("ldmatrix.sync.aligned.m8n8.x4.shared.b16 {%0,%1,%2,%3}, [%4];"
                 : "=r"(r0), "=r"(r1), "=r"(r2), "=r"(r3) : "r"(a));
}
__device__ __forceinline__ void mma16816(float* c, const uint32_t* a, const uint32_t* b) {
    asm volatile(
        "mma.sync.aligned.m16n8k16.row.col.f32.f16.f16.f32 "
        "{%0,%1,%2,%3}, {%4,%5,%6,%7}, {%8,%9}, {%0,%1,%2,%3};"
        : "+f"(c[0]), "+f"(c[1]), "+f"(c[2]), "+f"(c[3])
        : "r"(a[0]), "r"(a[1]), "r"(a[2]), "r"(a[3]), "r"(b[0]), "r"(b[1]));
}

// ---------------- prep kernels (globals bound in device code) ----------------
// per-level chunk: converts one level's tensor slice to fp16
__global__ void build_ah(int lvl, const float* __restrict__ X) {
    size_t base = (size_t)lvl * NN * DIN / 4;
    size_t i = base + (size_t)blockIdx.x * 256 + threadIdx.x;   // one float4 per thread
    float4 v = ((const float4*)X)[i];
    union { __half h[4]; uint2 u; } o;
    o.h[0] = __float2half(v.x); o.h[1] = __float2half(v.y);
    o.h[2] = __float2half(v.z); o.h[3] = __float2half(v.w);
    *(uint2*)&g_Ah[i * 4] = o.u;
}

__global__ void build_bw(const float* __restrict__ Ww, const float* __restrict__ Wb) {
    int t = blockIdx.x * blockDim.x + threadIdx.x;
    if (t < NWX) g_biasPerm[t] = Wb[((t & 3) << 7) + (t >> 2)];
    if (t >= NWX * DIN) return;
    int c = t >> 8, k = t & 255;
    int orig = ((c & 3) << 7) + (c >> 2);
    g_Bwh[t] = __float2half(Ww[orig * DIN + k]);
}

__global__ void build_upair(const float* __restrict__ Uf1,
                            const float* __restrict__ Uf2,
                            const float* __restrict__ Uiuo) {
    int t = blockIdx.x * blockDim.x + threadIdx.x;
    if (t >= NP * 128) return;
    int c = t >> 7;
    int k = t & 127;
    int half = c / 640;
    int r = c - half * 640;
    int w = r >> 7;
    int d = r & 127;
    int sc = half * 128 + k;
    float v;
    if (w == 0)      v = Uf1[d * DIN + sc];
    else if (w == 1) v = Uf2[d * DIN + sc];
    else             v = Uiuo[((w - 2) * DOUT + d) * DIN + sc];
    g_Upair[t] = v;
    g_Uph[t] = __float2half(v);
}

// one warp per output c, shuffle reduction
__global__ void build_pinit(const float* __restrict__ hInit) {
    int warp = (blockIdx.x * blockDim.x + threadIdx.x) >> 5;
    int lane = threadIdx.x & 31;
    if (warp >= NP) return;
    const float* row = g_Upair + (size_t)warp * 128;
    float s = 0.f;
#pragma unroll
    for (int k = 0; k < 4; k++) {
        int kk = lane + k * 32;
        s = fmaf(hInit[kk], row[kk], s);
    }
#pragma unroll
    for (int o = 16; o > 0; o >>= 1) s += __shfl_xor_sync(0xFFFFFFFF, s, o);
    if (lane == 0) g_Pinit[warp] = s;
}

// ---------------- fp16 mma.sync GEMM (single pass) ----------------
// MODE 0: X @ Ww -> g_WxH (fp16 out, +bias); mOff = level*64 row-block offset.
// MODE 1: H @ Upair -> g_P (fp32).
// Tiles: BM=BN=128, BK=32. 8 warps: wm=wid&1 (64 rows), wn=wid>>1 (32 cols).
// Smem row pitch 80B (32 fp16 + pad). 2 arrays/stage: A, B. 2 stages.
#define SM_PITCH 80
#define SM_ARR   10240              // 128 rows * 80B
#define SM_BUF   20480              // A, B
#define SM_TOT   40960

template<int MODE>
__global__ __launch_bounds__(256, 2) void mma_gemm(int mOff) {
    constexpr int K   = (MODE == 0) ? DIN : DOUT;
    constexpr int nCh = K / 32;
    constexpr int ldc = (MODE == 0) ? NWX : NP;

    const __half* __restrict__ A = (MODE == 0) ? g_Ah : g_Hh;
    const __half* __restrict__ B = (MODE == 0) ? g_Bwh : g_Uph;

    extern __shared__ char smem[];
    uint32_t sb = smem_to_u32(smem);
    int tid = threadIdx.x;
    int lane = tid & 31, wid = tid >> 5;
    int wm = wid & 1, wn = wid >> 1;
    int bn = blockIdx.x * 128;
    int bm = (mOff + blockIdx.y) * 128;

    float acc[4][4][4];
#pragma unroll
    for (int mi = 0; mi < 4; mi++)
#pragma unroll
        for (int ni = 0; ni < 4; ni++)
#pragma unroll
            for (int e = 0; e < 4; e++) acc[mi][ni][e] = 0.f;

    // cp.async: 512 16B-chunks per 128x32 fp16 array; 2 chunks/thread/array.
    int ch0 = tid * 2;
    int rowA0 = ch0 >> 2, cc0 = (ch0 & 3);
    int rowA1 = (ch0 + 1) >> 2, cc1 = ((ch0 + 1) & 3);
    const __half* gA0 = A + (size_t)(bm + rowA0) * K + cc0 * 8;
    const __half* gA1 = A + (size_t)(bm + rowA1) * K + cc1 * 8;
    const __half* gB0 = B + (size_t)(bn + rowA0) * K + cc0 * 8;
    const __half* gB1 = B + (size_t)(bn + rowA1) * K + cc1 * 8;
    uint32_t s0 = (uint32_t)(rowA0 * SM_PITCH + cc0 * 16);
    uint32_t s1 = (uint32_t)(rowA1 * SM_PITCH + cc1 * 16);

#define LOAD_STAGE(t, b) do {                                              \
    uint32_t bo = sb + (uint32_t)(b) * SM_BUF;                             \
    int ko = (t) * 32;                                                     \
    cpa16(bo + s0,            gA0 + ko);                                   \
    cpa16(bo + s1,            gA1 + ko);                                   \
    cpa16(bo + SM_ARR + s0,   gB0 + ko);                                   \
    cpa16(bo + SM_ARR + s1,   gB1 + ko);                                   \
} while (0)

    // ldmatrix lane addressing (verified in R8-R12)
    int q = lane >> 3, r = lane & 7;
    uint32_t aLane = (uint32_t)(wm * 64 * SM_PITCH + (r + (q & 1) * 8) * SM_PITCH + (q >> 1) * 16);
    uint32_t bLane = (uint32_t)(wn * 32 * SM_PITCH + ((q >> 1) * 8 + r) * SM_PITCH + (q & 1) * 16);

    LOAD_STAGE(0, 0); CP_COMMIT();
    if (nCh > 1) { LOAD_STAGE(1, 1); CP_COMMIT(); }

    for (int t = 0; t < nCh; t++) {
        if (t == nCh - 1) asm volatile("cp.async.wait_group 0;" ::: "memory");
        else              asm volatile("cp.async.wait_group 1;" ::: "memory");
        __syncthreads();

        uint32_t base = sb + (uint32_t)(t & 1) * SM_BUF;
#pragma unroll
        for (int ks = 0; ks < 2; ks++) {
            uint32_t a[4][4], b[4][2];
#pragma unroll
            for (int mi = 0; mi < 4; mi++)
                ldm_x4(base + aLane + mi * (16 * SM_PITCH) + ks * 32,
                       a[mi][0], a[mi][1], a[mi][2], a[mi][3]);
#pragma unroll
            for (int np = 0; np < 2; np++) {
                uint32_t r0, r1, r2, r3;
                ldm_x4(base + SM_ARR + bLane + np * (16 * SM_PITCH) + ks * 32, r0, r1, r2, r3);
                b[2 * np][0] = r0; b[2 * np][1] = r1;
                b[2 * np + 1][0] = r2; b[2 * np + 1][1] = r3;
            }
#pragma unroll
            for (int mi = 0; mi < 4; mi++)
#pragma unroll
                for (int ni = 0; ni < 4; ni++)
                    mma16816(acc[mi][ni], a[mi], b[ni]);
        }
        __syncthreads();
        if (t + 2 < nCh) { LOAD_STAGE(t + 2, t & 1); CP_COMMIT(); }
    }

    // epilogue
    int g = lane >> 2, tc = lane & 3;
#pragma unroll
    for (int mi = 0; mi < 4; mi++) {
        int row0 = bm + wm * 64 + mi * 16 + g;
#pragma unroll
        for (int ni = 0; ni < 4; ni++) {
            int col = bn + wn * 32 + ni * 8 + tc * 2;
            if (MODE == 0) {
                float b0 = g_biasPerm[col], b1 = g_biasPerm[col + 1];
                __half2 h0 = __floats2half2_rn(acc[mi][ni][0] + b0, acc[mi][ni][1] + b1);
                __half2 h1 = __floats2half2_rn(acc[mi][ni][2] + b0, acc[mi][ni][3] + b1);
                *(__half2*)&g_WxH[(size_t)row0 * ldc + col] = h0;
                *(__half2*)&g_WxH[(size_t)(row0 + 8) * ldc + col] = h1;
            } else {
                float2 v0, v1;
                v0.x = acc[mi][ni][0]; v0.y = acc[mi][ni][1];
                v1.x = acc[mi][ni][2]; v1.y = acc[mi][ni][3];
                *(float2*)&g_P[(size_t)row0 * ldc + col] = v0;
                *(float2*)&g_P[(size_t)(row0 + 8) * ldc + col] = v1;
            }
        }
    }
#undef LOAD_STAGE
}

// ---------------- LSTM gate epilogue ----------------
__global__ __launch_bounds__(256) void epilogue_kernel(
    int lvl,
    const int* __restrict__ indices,
    const float* __restrict__ cInit,
    float* __restrict__ outH,
    float* __restrict__ outC)
{
    int tid = threadIdx.x;
    int n = blockIdx.x * 2 + (tid >> 7);
    int d = tid & 127;

    int i0 = indices[((size_t)lvl * NN + n) * 2 + 0];
    int i1 = indices[((size_t)lvl * NN + n) * 2 + 1];
    bool L0 = (lvl == 0);

    float p0[5], p1[5];
    if (!L0 && i0 >= 0) {
        const float* rr = g_P + (size_t)i0 * NP;
#pragma unroll
        for (int w = 0; w < 5; w++) p0[w] = rr[w * 128 + d];
    } else {
#pragma unroll
        for (int w = 0; w < 5; w++) p0[w] = g_Pinit[w * 128 + d];
    }
    if (!L0 && i1 >= 0) {
        const float* rr = g_P + (size_t)i1 * NP + 640;
#pragma unroll
        for (int w = 0; w < 5; w++) p1[w] = rr[w * 128 + d];
    } else {
#pragma unroll
        for (int w = 0; w < 5; w++) p1[w] = g_Pinit[640 + w * 128 + d];
    }

    // g_WxH: 4 fp16 per (n,d): f_x, i_x, u_x, o_x
    union { uint2 u; __half h[4]; } wv;
    wv.u = *(const uint2*)&g_WxH[(((size_t)lvl * NN + n) << 9) + (d << 2)];
    float fx = __half2float(wv.h[0]);
    float ix = __half2float(wv.h[1]);
    float ux = __half2float(wv.h[2]);
    float ox = __half2float(wv.h[3]);

    float f1 = sigmoidf_(fx + p0[0] + p1[0]);
    float f2 = sigmoidf_(fx + p0[1] + p1[1]);
    float ig = sigmoidf_(ix + p0[2] + p1[2]);
    float ug = tanhf(ux + p0[3] + p1[3]);
    float og = sigmoidf_(ox + p0[4] + p1[4]);

    const float* prevC = outC + (size_t)(lvl - 1) * NN * DOUT;
    float cc0 = (!L0 && i0 >= 0) ? prevC[(size_t)i0 * DOUT + d] : cInit[d];
    float cc1 = (!L0 && i1 >= 0) ? prevC[(size_t)i1 * DOUT + d] : cInit[d];

    float nc = ig * ug + f1 * cc0 + f2 * cc1;
    float nh = og * tanhf(nc);

    size_t o = ((size_t)lvl * NN + n) * DOUT + d;
    outH[o] = nh;
    outC[o] = nc;

    // fp16 copy of h for the next level's tensor-core GEMM
    g_Hh[(size_t)n * DOUT + d] = __float2half(nh);
}

extern "C" void kernel_launch(void* const* d_in, const int* in_sizes, int n_in,
                              void* d_out, int out_size) {
    const float* tensor = (const float*)d_in[0];   // [L, N, DIN]
    const int*   indices = (const int*)d_in[1];    // [L, N, 2]
    const float* h_init = (const float*)d_in[2];   // [1, DOUT]
    const float* c_init = (const float*)d_in[3];   // [1, DOUT]
    const float* W_w   = (const float*)d_in[4];    // [4*DOUT, DIN]
    const float* W_b   = (const float*)d_in[5];    // [4*DOUT]
    const float* U_f1  = (const float*)d_in[6];    // [DOUT, 2*DOUT]
    const float* U_f2  = (const float*)d_in[7];
    const float* U_iuo = (const float*)d_in[8];    // [3*DOUT, 2*DOUT]

    float* outH = (float*)d_out;                         // res_h [L,N,DOUT]
    float* outC = outH + (size_t)LL * NN * DOUT;         // res_c [L,N,DOUT]

    cudaFuncSetAttribute(mma_gemm<0>, cudaFuncAttributeMaxDynamicSharedMemorySize, SM_TOT);
    cudaFuncSetAttribute(mma_gemm<1>, cudaFuncAttributeMaxDynamicSharedMemorySize, SM_TOT);

    cudaStream_t s1 = g_res.s1;

    // main stream: weight prep needed by side stream first
    build_bw<<<(NWX * DIN + 255) / 256, 256>>>(W_w, W_b);
    cudaEventRecord(g_res.evStart, 0);

    // side stream: per-level tensor convert + pre-GEMM chunks
    cudaStreamWaitEvent(s1, g_res.evStart, 0);
    for (int lvl = 0; lvl < LL; lvl++) {
        build_ah<<<NN * DIN / 4 / 256, 256, 0, s1>>>(lvl, tensor);
        dim3 g(NWX / 128, 64);
        mma_gemm<0><<<g, 256, SM_TOT, s1>>>(lvl * 64);
        cudaEventRecord(g_res.ev[lvl], s1);
    }

    // main stream: remaining prep + recurrent chain
    build_upair<<<(NP * 128 + 255) / 256, 256>>>(U_f1, U_f2, U_iuo);
    build_pinit<<<(NP * 32 + 255) / 256, 256>>>(h_init);

    dim3 pg(NP / 128, NN / 128);                         // (10, 64)
    for (int lvl = 0; lvl < LL; lvl++) {
        if (lvl > 0) {
            mma_gemm<1><<<pg, 256, SM_TOT>>>(0);
        }
        cudaStreamWaitEvent(0, g_res.ev[lvl], 0);
        epilogue_kernel<<<NN / 2, 256>>>(lvl, indices, c_init, outH, outC);
    }
}